// round 15
// baseline (speedup 1.0000x reference)
#include <cuda_runtime.h>
#include <cuda_fp16.h>

#define NB 2
#define DD 160
#define HH 192
#define WW 224
#define SLICE (HH*WW)          // 43008
#define VOL   (DD*SLICE)       // 6881280
#define TOT   (NB*VOL)         // 13762560

#define W0 0.05448868454964294f
#define W1 0.24420134200323332f
#define W2 0.40261994689424753f

// Interleaved fp16 mid: channels 0..3 packed as uint4 (4x half2) per x-pair,
// channel 4 separate as half2. Indexed by idx2 = n*(VOL/2) + s*(SLICE/2) + p2.
__device__ uint4     g_mid4[TOT / 2];    // 110 MB
__device__ __half2   g_midc[TOT / 2];    // 27.5 MB
__device__ double    g_sum[2];
__device__ unsigned  g_ticket = 0;

// ---------------------------------------------------------------------------
// packed f32x2 helpers (sm_103a): full fp32 precision, 2x rate.
// ---------------------------------------------------------------------------
__device__ __forceinline__ float2 add2(float2 a, float2 b) {
    float2 d;
    asm("{\n\t.reg .b64 x,y,w;\n\t"
        "mov.b64 x,{%2,%3};\n\tmov.b64 y,{%4,%5};\n\t"
        "add.rn.f32x2 w,x,y;\n\tmov.b64 {%0,%1},w;\n\t}"
        : "=f"(d.x), "=f"(d.y)
        : "f"(a.x), "f"(a.y), "f"(b.x), "f"(b.y));
    return d;
}
__device__ __forceinline__ float2 mul2(float2 a, float2 b) {
    float2 d;
    asm("{\n\t.reg .b64 x,y,w;\n\t"
        "mov.b64 x,{%2,%3};\n\tmov.b64 y,{%4,%5};\n\t"
        "mul.rn.f32x2 w,x,y;\n\tmov.b64 {%0,%1},w;\n\t}"
        : "=f"(d.x), "=f"(d.y)
        : "f"(a.x), "f"(a.y), "f"(b.x), "f"(b.y));
    return d;
}
__device__ __forceinline__ float2 fma2(float2 a, float2 b, float2 c) {
    float2 d;
    asm("{\n\t.reg .b64 x,y,z,w;\n\t"
        "mov.b64 x,{%2,%3};\n\tmov.b64 y,{%4,%5};\n\tmov.b64 z,{%6,%7};\n\t"
        "fma.rn.f32x2 w,x,y,z;\n\tmov.b64 {%0,%1},w;\n\t}"
        : "=f"(d.x), "=f"(d.y)
        : "f"(a.x), "f"(a.y), "f"(b.x), "f"(b.y), "f"(c.x), "f"(c.y));
    return d;
}

__device__ __forceinline__ float2 blur5(float2 v0, float2 v1, float2 v2,
                                        float2 v3, float2 v4,
                                        float2 w0, float2 w1, float2 w2)
{
    float2 t = add2(v0, v4);
    float2 u = add2(v1, v3);
    float2 s = mul2(w0, t);
    s = fma2(w1, u, s);
    s = fma2(w2, v2, s);
    return s;
}

// half2 blur for the D axis (B kernel). LNCC is scale-invariant, so fp16
// weight rounding cancels; random rounding averages out in the reduction.
__device__ __forceinline__ __half2 blur5h(__half2 v0, __half2 v1, __half2 v2,
                                          __half2 v3, __half2 v4,
                                          __half2 w0, __half2 w1, __half2 w2)
{
    __half2 s = __hmul2(w0, __hadd2(v0, v4));
    s = __hfma2(w1, __hadd2(v1, v3), s);
    s = __hfma2(w2, v2, s);
    return s;
}

// ---------------------------------------------------------------------------
// Kernel A: per (n,d) slice, fused W+H blur of the 5 channels, x-pair packed.
// (R11 version — best measured A.)
// ---------------------------------------------------------------------------
#define SPITCH 19   // stage pitch in float2 pairs (18 used)
#define WPITCH 24   // sw pitch in half2 (16 used)

__global__ void __launch_bounds__(256) lncc_blur_wh(const float* __restrict__ I,
                                                    const float* __restrict__ J)
{
    __shared__ float2  sa[36][SPITCH];
    __shared__ float2  sb[36][SPITCH];
    __shared__ __half2 sw[5][36][WPITCH];

    const int tid = threadIdx.x;
    const int nd  = blockIdx.z;                 // n*DD + d
    const int gx0 = blockIdx.x * 32;
    const int gy0 = blockIdx.y * 32;

    if (nd == 0 && blockIdx.x == 0 && blockIdx.y == 0 && tid == 0) {
        g_sum[0] = 0.0;
        g_sum[1] = 0.0;
        g_ticket = 0u;
    }

    const float* __restrict__ Ib = I + (size_t)nd * SLICE;
    const float* __restrict__ Jb = J + (size_t)nd * SLICE;

    const float2 w0 = make_float2(W0, W0);
    const float2 w1 = make_float2(W1, W1);
    const float2 w2 = make_float2(W2, W2);

    // ---- stage raw a,b as x-pairs with halo (zero padding) ----
    for (int i = tid; i < 36 * 18; i += 256) {
        int row = i / 18;
        int p   = i - row * 18;
        int gy  = gy0 + row - 2;
        int gx  = gx0 + 2 * p - 2;        // even; pair never straddles bounds
        float2 a = make_float2(0.f, 0.f);
        float2 b = make_float2(0.f, 0.f);
        if ((unsigned)gy < HH && (unsigned)gx < WW) {
            const int o = gy * WW + gx;
            a = *reinterpret_cast<const float2*>(Ib + o);
            b = *reinterpret_cast<const float2*>(Jb + o);
        }
        sa[row][p] = a;
        sb[row][p] = b;
    }
    __syncthreads();

    // ---- W blur: 36 rows x 16 out-pairs; odd taps via register repack ----
    for (int i = tid; i < 36 * 16; i += 256) {
        int r = i >> 4;
        int q = i & 15;

        float2 va0 = sa[r][q], va2 = sa[r][q + 1], va4 = sa[r][q + 2];
        float2 vb0 = sb[r][q], vb2 = sb[r][q + 1], vb4 = sb[r][q + 2];
        float2 va1 = make_float2(va0.y, va2.x);
        float2 va3 = make_float2(va2.y, va4.x);
        float2 vb1 = make_float2(vb0.y, vb2.x);
        float2 vb3 = make_float2(vb2.y, vb4.x);

        float2 ab0 = mul2(va0, vb0), ab1 = mul2(va1, vb1), ab2 = mul2(va2, vb2),
               ab3 = mul2(va3, vb3), ab4 = mul2(va4, vb4);
        float2 aa0 = mul2(va0, va0), aa1 = mul2(va1, va1), aa2 = mul2(va2, va2),
               aa3 = mul2(va3, va3), aa4 = mul2(va4, va4);
        float2 bb0 = mul2(vb0, vb0), bb1 = mul2(vb1, vb1), bb2 = mul2(vb2, vb2),
               bb3 = mul2(vb3, vb3), bb4 = mul2(vb4, vb4);

        float2 s0 = blur5(va0, va1, va2, va3, va4, w0, w1, w2);
        float2 s1 = blur5(vb0, vb1, vb2, vb3, vb4, w0, w1, w2);
        float2 s2 = blur5(ab0, ab1, ab2, ab3, ab4, w0, w1, w2);
        float2 s3 = blur5(aa0, aa1, aa2, aa3, aa4, w0, w1, w2);
        float2 s4 = blur5(bb0, bb1, bb2, bb3, bb4, w0, w1, w2);
        sw[0][r][q] = __floats2half2_rn(s0.x, s0.y);
        sw[1][r][q] = __floats2half2_rn(s1.x, s1.y);
        sw[2][r][q] = __floats2half2_rn(s2.x, s2.y);
        sw[3][r][q] = __floats2half2_rn(s3.x, s3.y);
        sw[4][r][q] = __floats2half2_rn(s4.x, s4.y);
    }
    __syncthreads();

    // ---- H blur: thread owns out-pair column q, y-outputs y0, y0+1 ----
    const int q  = tid & 15;
    const int y0 = (tid >> 4) * 2;

    const size_t obase2 = ((size_t)nd * SLICE) / 2 + (size_t)(gx0 >> 1) + q;

    __half2 h0[5], h1[5];
    #pragma unroll
    for (int c = 0; c < 5; c++) {
        float2 t0 = __half22float2(sw[c][y0    ][q]);
        float2 t1 = __half22float2(sw[c][y0 + 1][q]);
        float2 t2 = __half22float2(sw[c][y0 + 2][q]);
        float2 t3 = __half22float2(sw[c][y0 + 3][q]);
        float2 t4 = __half22float2(sw[c][y0 + 4][q]);
        float2 t5 = __half22float2(sw[c][y0 + 5][q]);
        float2 o0 = blur5(t0, t1, t2, t3, t4, w0, w1, w2);
        float2 o1 = blur5(t1, t2, t3, t4, t5, w0, w1, w2);
        h0[c] = __floats2half2_rn(o0.x, o0.y);
        h1[c] = __floats2half2_rn(o1.x, o1.y);
    }

    const size_t i0 = obase2 + (size_t)(gy0 + y0)     * (WW / 2);
    const size_t i1 = obase2 + (size_t)(gy0 + y0 + 1) * (WW / 2);
    uint4 u0, u1;
    *reinterpret_cast<__half2*>(&u0.x) = h0[0];
    *reinterpret_cast<__half2*>(&u0.y) = h0[1];
    *reinterpret_cast<__half2*>(&u0.z) = h0[2];
    *reinterpret_cast<__half2*>(&u0.w) = h0[3];
    *reinterpret_cast<__half2*>(&u1.x) = h1[0];
    *reinterpret_cast<__half2*>(&u1.y) = h1[1];
    *reinterpret_cast<__half2*>(&u1.z) = h1[2];
    *reinterpret_cast<__half2*>(&u1.w) = h1[3];
    g_mid4[i0] = u0;
    g_midc[i0] = h0[4];
    g_mid4[i1] = u1;
    g_midc[i1] = h1[4];
}

// ---------------------------------------------------------------------------
// Kernel B: D-marching blur. Rolling buffer held as raw half2 (25 regs),
// D-blur in half2 arithmetic (scale-invariance makes fp16 weights safe),
// LNCC in fp32. Slices + mask prefetched one iteration ahead.
// ---------------------------------------------------------------------------
#define DSEG 20
#define NSEG (DD/DSEG)             // 8
#define P2   (SLICE/2)             // 21504
#define BLK_P (P2/256)             // 84
#define NBLK_B (NB*NSEG*BLK_P)     // 1344

__device__ __forceinline__ void load_slice_h(const uint4* p4, const __half2* pc,
                                             size_t o, bool ok, __half2* dst)
{
    if (ok) {
        const uint4 u = p4[o];
        dst[0] = *reinterpret_cast<const __half2*>(&u.x);
        dst[1] = *reinterpret_cast<const __half2*>(&u.y);
        dst[2] = *reinterpret_cast<const __half2*>(&u.z);
        dst[3] = *reinterpret_cast<const __half2*>(&u.w);
        dst[4] = pc[o];
    } else {
        const __half2 z = __float2half2_rn(0.f);
        #pragma unroll
        for (int c = 0; c < 5; c++) dst[c] = z;
    }
}

__global__ void __launch_bounds__(256, 4) lncc_d_march(const float* __restrict__ M,
                                                       float* __restrict__ out)
{
    const int blk = blockIdx.x;
    const int n   = blk / (NSEG * BLK_P);
    const int r   = blk - n * (NSEG * BLK_P);
    const int seg = r / BLK_P;
    const int pb  = r - seg * BLK_P;
    const int p2  = pb * 256 + threadIdx.x;
    const int d0  = seg * DSEG;                // multiple of 5

    const __half2 hw0 = __float2half2_rn(W0);
    const __half2 hw1 = __float2half2_rn(W1);
    const __half2 hw2 = __float2half2_rn(W2);

    const uint4*   __restrict__ p4 = g_mid4 + (size_t)n * (VOL / 2) + p2;
    const __half2* __restrict__ pc = g_midc + (size_t)n * (VOL / 2) + p2;

    __half2 v[5][5];   // [channel][slot], slot(s) = (s+2) mod 5
    __half2 t[5];      // prefetched slice
    float2  mk;        // prefetched mask pair

    // ---- prologue: slices d0-2 .. d0+2 -> slots 0..4 ----
    #pragma unroll
    for (int i = 0; i < 5; i++) {
        const int s = d0 - 2 + i;
        const bool ok = (unsigned)s < DD;
        const size_t o = (size_t)(ok ? s : 0) * (SLICE / 2);
        __half2 tmp[5];
        load_slice_h(p4, pc, o, ok, tmp);
        #pragma unroll
        for (int c = 0; c < 5; c++) v[c][i] = tmp[c];
    }
    const float* __restrict__ Mp = M + (size_t)n * VOL + 2u * (size_t)p2
                                     + (size_t)d0 * SLICE;
    // prefetch slice d0+3 and mask for od = d0
    {
        const int s = d0 + 3;
        const bool ok = (unsigned)s < DD;
        const size_t o = (size_t)(ok ? s : 0) * (SLICE / 2);
        load_slice_h(p4, pc, o, ok, t);
        mk = *reinterpret_cast<const float2*>(Mp);
    }

    float sl = 0.f, sm = 0.f;

    // ---- main loop: 20 outputs, 4 groups of 5 (slot indices static) ----
    #pragma unroll
    for (int g = 0; g < 4; g++) {
        #pragma unroll
        for (int u = 0; u < 5; u++) {
            const int k  = g * 5 + u;
            const int od = d0 + k;

            // 1) blur in half2, convert results to fp32
            float2 a[5];
            #pragma unroll
            for (int c = 0; c < 5; c++) {
                __half2 bh = blur5h(v[c][(u + 0) % 5], v[c][(u + 1) % 5],
                                    v[c][(u + 2) % 5], v[c][(u + 3) % 5],
                                    v[c][(u + 4) % 5], hw0, hw1, hw2);
                a[c] = __half22float2(bh);
            }

            {
                float cross = a[2].x - a[0].x * a[1].x;
                float varI  = fmaxf(a[3].x - a[0].x * a[0].x, 0.f) + 1e-5f;
                float varJ  = fmaxf(a[4].x - a[1].x * a[1].x, 0.f) + 1e-5f;
                float lncc  = 1.f - cross * rsqrtf(varI * varJ);
                sl += lncc * mk.x;
                sm += mk.x;
            }
            {
                float cross = a[2].y - a[0].y * a[1].y;
                float varI  = fmaxf(a[3].y - a[0].y * a[0].y, 0.f) + 1e-5f;
                float varJ  = fmaxf(a[4].y - a[1].y * a[1].y, 0.f) + 1e-5f;
                float lncc  = 1.f - cross * rsqrtf(varI * varJ);
                sl += lncc * mk.y;
                sm += mk.y;
            }

            // 2) commit prefetched slice od+3 into slot u (was od-2, now dead)
            #pragma unroll
            for (int c = 0; c < 5; c++) v[c][u] = t[c];

            // 3) issue prefetch of slice od+4 and mask of od+1
            {
                const int s = od + 4;
                const bool ok = (unsigned)s < DD;
                const size_t o = (size_t)(ok ? s : 0) * (SLICE / 2);
                load_slice_h(p4, pc, o, ok, t);
                const int kn = (k < DSEG - 1) ? k + 1 : k;   // stay in-bounds
                mk = *reinterpret_cast<const float2*>(Mp + (size_t)kn * SLICE);
            }
        }
    }

    // ---- block reduction ----
    #pragma unroll
    for (int o = 16; o > 0; o >>= 1) {
        sl += __shfl_down_sync(0xFFFFFFFFu, sl, o);
        sm += __shfl_down_sync(0xFFFFFFFFu, sm, o);
    }
    __shared__ float rl[8], rm[8];
    const int lane = threadIdx.x & 31, wid = threadIdx.x >> 5;
    if (lane == 0) { rl[wid] = sl; rm[wid] = sm; }
    __syncthreads();
    if (threadIdx.x == 0) {
        float tl = 0.f, tm = 0.f;
        #pragma unroll
        for (int i = 0; i < 8; i++) { tl += rl[i]; tm += rm[i]; }
        atomicAdd(&g_sum[0], (double)tl);
        atomicAdd(&g_sum[1], (double)tm);
        __threadfence();
        const unsigned tk = atomicAdd(&g_ticket, 1u);
        if (tk == (unsigned)(NBLK_B - 1)) {
            const double s0 = atomicAdd(&g_sum[0], 0.0);
            const double s1 = atomicAdd(&g_sum[1], 0.0);
            out[0] = (float)(s0 / (s1 + 1e-8));
        }
    }
}

// ---------------------------------------------------------------------------

extern "C" void kernel_launch(void* const* d_in, const int* in_sizes, int n_in,
                              void* d_out, int out_size)
{
    const float* A = (const float*)d_in[0];  // image_A
    const float* B = (const float*)d_in[1];  // image_B
    const float* M = (const float*)d_in[2];  // mask_A
    float* out = (float*)d_out;

    dim3 gA(WW / 32, HH / 32, NB * DD);      // (7, 6, 320)
    lncc_blur_wh<<<gA, 256>>>(A, B);

    lncc_d_march<<<NBLK_B, 256>>>(M, out);
}

// round 16
// speedup vs baseline: 1.3113x; 1.3113x over previous
#include <cuda_runtime.h>
#include <cuda_fp16.h>

#define NB 2
#define DD 160
#define HH 192
#define WW 224
#define SLICE (HH*WW)          // 43008
#define VOL   (DD*SLICE)       // 6881280
#define TOT   (NB*VOL)         // 13762560

#define W0 0.05448868454964294f
#define W1 0.24420134200323332f
#define W2 0.40261994689424753f

// Interleaved fp16 mid: channels 0..3 packed as uint4 (4x half2) per x-pair,
// channel 4 separate as half2. Indexed by idx2 = n*(VOL/2) + s*(SLICE/2) + p2.
__device__ uint4     g_mid4[TOT / 2];    // 110 MB
__device__ __half2   g_midc[TOT / 2];    // 27.5 MB
__device__ double    g_sum[2];
__device__ unsigned  g_ticket = 0;

// ---------------------------------------------------------------------------
// packed f32x2 helpers (sm_103a): full fp32 precision, 2x rate.
// ---------------------------------------------------------------------------
__device__ __forceinline__ float2 add2(float2 a, float2 b) {
    float2 d;
    asm("{\n\t.reg .b64 x,y,w;\n\t"
        "mov.b64 x,{%2,%3};\n\tmov.b64 y,{%4,%5};\n\t"
        "add.rn.f32x2 w,x,y;\n\tmov.b64 {%0,%1},w;\n\t}"
        : "=f"(d.x), "=f"(d.y)
        : "f"(a.x), "f"(a.y), "f"(b.x), "f"(b.y));
    return d;
}
__device__ __forceinline__ float2 mul2(float2 a, float2 b) {
    float2 d;
    asm("{\n\t.reg .b64 x,y,w;\n\t"
        "mov.b64 x,{%2,%3};\n\tmov.b64 y,{%4,%5};\n\t"
        "mul.rn.f32x2 w,x,y;\n\tmov.b64 {%0,%1},w;\n\t}"
        : "=f"(d.x), "=f"(d.y)
        : "f"(a.x), "f"(a.y), "f"(b.x), "f"(b.y));
    return d;
}
__device__ __forceinline__ float2 fma2(float2 a, float2 b, float2 c) {
    float2 d;
    asm("{\n\t.reg .b64 x,y,z,w;\n\t"
        "mov.b64 x,{%2,%3};\n\tmov.b64 y,{%4,%5};\n\tmov.b64 z,{%6,%7};\n\t"
        "fma.rn.f32x2 w,x,y,z;\n\tmov.b64 {%0,%1},w;\n\t}"
        : "=f"(d.x), "=f"(d.y)
        : "f"(a.x), "f"(a.y), "f"(b.x), "f"(b.y), "f"(c.x), "f"(c.y));
    return d;
}

__device__ __forceinline__ float2 blur5(float2 v0, float2 v1, float2 v2,
                                        float2 v3, float2 v4,
                                        float2 w0, float2 w1, float2 w2)
{
    float2 t = add2(v0, v4);
    float2 u = add2(v1, v3);
    float2 s = mul2(w0, t);
    s = fma2(w1, u, s);
    s = fma2(w2, v2, s);
    return s;
}

// half2 blur for the D axis (B kernel). LNCC is scale-invariant, so fp16
// weight rounding cancels; random rounding averages out in the reduction.
__device__ __forceinline__ __half2 blur5h(__half2 v0, __half2 v1, __half2 v2,
                                          __half2 v3, __half2 v4,
                                          __half2 w0, __half2 w1, __half2 w2)
{
    __half2 s = __hmul2(w0, __hadd2(v0, v4));
    s = __hfma2(w1, __hadd2(v1, v3), s);
    s = __hfma2(w2, v2, s);
    return s;
}

// ---------------------------------------------------------------------------
// Kernel A: per (n,d) slice, fused W+H blur of the 5 channels, x-pair packed.
// (R11 version — best measured A.)
// ---------------------------------------------------------------------------
#define SPITCH 19   // stage pitch in float2 pairs (18 used)
#define WPITCH 24   // sw pitch in half2 (16 used)

__global__ void __launch_bounds__(256) lncc_blur_wh(const float* __restrict__ I,
                                                    const float* __restrict__ J)
{
    __shared__ float2  sa[36][SPITCH];
    __shared__ float2  sb[36][SPITCH];
    __shared__ __half2 sw[5][36][WPITCH];

    const int tid = threadIdx.x;
    const int nd  = blockIdx.z;                 // n*DD + d
    const int gx0 = blockIdx.x * 32;
    const int gy0 = blockIdx.y * 32;

    if (nd == 0 && blockIdx.x == 0 && blockIdx.y == 0 && tid == 0) {
        g_sum[0] = 0.0;
        g_sum[1] = 0.0;
        g_ticket = 0u;
    }

    const float* __restrict__ Ib = I + (size_t)nd * SLICE;
    const float* __restrict__ Jb = J + (size_t)nd * SLICE;

    const float2 w0 = make_float2(W0, W0);
    const float2 w1 = make_float2(W1, W1);
    const float2 w2 = make_float2(W2, W2);

    // ---- stage raw a,b as x-pairs with halo (zero padding) ----
    for (int i = tid; i < 36 * 18; i += 256) {
        int row = i / 18;
        int p   = i - row * 18;
        int gy  = gy0 + row - 2;
        int gx  = gx0 + 2 * p - 2;        // even; pair never straddles bounds
        float2 a = make_float2(0.f, 0.f);
        float2 b = make_float2(0.f, 0.f);
        if ((unsigned)gy < HH && (unsigned)gx < WW) {
            const int o = gy * WW + gx;
            a = *reinterpret_cast<const float2*>(Ib + o);
            b = *reinterpret_cast<const float2*>(Jb + o);
        }
        sa[row][p] = a;
        sb[row][p] = b;
    }
    __syncthreads();

    // ---- W blur: 36 rows x 16 out-pairs; odd taps via register repack ----
    for (int i = tid; i < 36 * 16; i += 256) {
        int r = i >> 4;
        int q = i & 15;

        float2 va0 = sa[r][q], va2 = sa[r][q + 1], va4 = sa[r][q + 2];
        float2 vb0 = sb[r][q], vb2 = sb[r][q + 1], vb4 = sb[r][q + 2];
        float2 va1 = make_float2(va0.y, va2.x);
        float2 va3 = make_float2(va2.y, va4.x);
        float2 vb1 = make_float2(vb0.y, vb2.x);
        float2 vb3 = make_float2(vb2.y, vb4.x);

        float2 ab0 = mul2(va0, vb0), ab1 = mul2(va1, vb1), ab2 = mul2(va2, vb2),
               ab3 = mul2(va3, vb3), ab4 = mul2(va4, vb4);
        float2 aa0 = mul2(va0, va0), aa1 = mul2(va1, va1), aa2 = mul2(va2, va2),
               aa3 = mul2(va3, va3), aa4 = mul2(va4, va4);
        float2 bb0 = mul2(vb0, vb0), bb1 = mul2(vb1, vb1), bb2 = mul2(vb2, vb2),
               bb3 = mul2(vb3, vb3), bb4 = mul2(vb4, vb4);

        float2 s0 = blur5(va0, va1, va2, va3, va4, w0, w1, w2);
        float2 s1 = blur5(vb0, vb1, vb2, vb3, vb4, w0, w1, w2);
        float2 s2 = blur5(ab0, ab1, ab2, ab3, ab4, w0, w1, w2);
        float2 s3 = blur5(aa0, aa1, aa2, aa3, aa4, w0, w1, w2);
        float2 s4 = blur5(bb0, bb1, bb2, bb3, bb4, w0, w1, w2);
        sw[0][r][q] = __floats2half2_rn(s0.x, s0.y);
        sw[1][r][q] = __floats2half2_rn(s1.x, s1.y);
        sw[2][r][q] = __floats2half2_rn(s2.x, s2.y);
        sw[3][r][q] = __floats2half2_rn(s3.x, s3.y);
        sw[4][r][q] = __floats2half2_rn(s4.x, s4.y);
    }
    __syncthreads();

    // ---- H blur: thread owns out-pair column q, y-outputs y0, y0+1 ----
    const int q  = tid & 15;
    const int y0 = (tid >> 4) * 2;

    const size_t obase2 = ((size_t)nd * SLICE) / 2 + (size_t)(gx0 >> 1) + q;

    __half2 h0[5], h1[5];
    #pragma unroll
    for (int c = 0; c < 5; c++) {
        float2 t0 = __half22float2(sw[c][y0    ][q]);
        float2 t1 = __half22float2(sw[c][y0 + 1][q]);
        float2 t2 = __half22float2(sw[c][y0 + 2][q]);
        float2 t3 = __half22float2(sw[c][y0 + 3][q]);
        float2 t4 = __half22float2(sw[c][y0 + 4][q]);
        float2 t5 = __half22float2(sw[c][y0 + 5][q]);
        float2 o0 = blur5(t0, t1, t2, t3, t4, w0, w1, w2);
        float2 o1 = blur5(t1, t2, t3, t4, t5, w0, w1, w2);
        h0[c] = __floats2half2_rn(o0.x, o0.y);
        h1[c] = __floats2half2_rn(o1.x, o1.y);
    }

    const size_t i0 = obase2 + (size_t)(gy0 + y0)     * (WW / 2);
    const size_t i1 = obase2 + (size_t)(gy0 + y0 + 1) * (WW / 2);
    uint4 u0, u1;
    *reinterpret_cast<__half2*>(&u0.x) = h0[0];
    *reinterpret_cast<__half2*>(&u0.y) = h0[1];
    *reinterpret_cast<__half2*>(&u0.z) = h0[2];
    *reinterpret_cast<__half2*>(&u0.w) = h0[3];
    *reinterpret_cast<__half2*>(&u1.x) = h1[0];
    *reinterpret_cast<__half2*>(&u1.y) = h1[1];
    *reinterpret_cast<__half2*>(&u1.z) = h1[2];
    *reinterpret_cast<__half2*>(&u1.w) = h1[3];
    g_mid4[i0] = u0;
    g_midc[i0] = h0[4];
    g_mid4[i1] = u1;
    g_midc[i1] = h1[4];
}

// ---------------------------------------------------------------------------
// Kernel B: D-marching blur. Rolling buffer held as raw half2 (25 regs),
// D-blur in half2 arithmetic (scale-invariance makes fp16 weights safe),
// LNCC in fp32. Slices + mask prefetched one iteration ahead.
// ---------------------------------------------------------------------------
#define DSEG 20
#define NSEG (DD/DSEG)             // 8
#define P2   (SLICE/2)             // 21504
#define BLK_P (P2/256)             // 84
#define NBLK_B (NB*NSEG*BLK_P)     // 1344

__device__ __forceinline__ void load_slice_h(const uint4* p4, const __half2* pc,
                                             size_t o, bool ok, __half2* dst)
{
    if (ok) {
        const uint4 u = p4[o];
        dst[0] = *reinterpret_cast<const __half2*>(&u.x);
        dst[1] = *reinterpret_cast<const __half2*>(&u.y);
        dst[2] = *reinterpret_cast<const __half2*>(&u.z);
        dst[3] = *reinterpret_cast<const __half2*>(&u.w);
        dst[4] = pc[o];
    } else {
        const __half2 z = __float2half2_rn(0.f);
        #pragma unroll
        for (int c = 0; c < 5; c++) dst[c] = z;
    }
}

__global__ void __launch_bounds__(256, 4) lncc_d_march(const float* __restrict__ M,
                                                       float* __restrict__ out)
{
    const int blk = blockIdx.x;
    const int n   = blk / (NSEG * BLK_P);
    const int r   = blk - n * (NSEG * BLK_P);
    const int seg = r / BLK_P;
    const int pb  = r - seg * BLK_P;
    const int p2  = pb * 256 + threadIdx.x;
    const int d0  = seg * DSEG;                // multiple of 5

    const __half2 hw0 = __float2half2_rn(W0);
    const __half2 hw1 = __float2half2_rn(W1);
    const __half2 hw2 = __float2half2_rn(W2);

    const uint4*   __restrict__ p4 = g_mid4 + (size_t)n * (VOL / 2) + p2;
    const __half2* __restrict__ pc = g_midc + (size_t)n * (VOL / 2) + p2;

    __half2 v[5][5];   // [channel][slot], slot(s) = (s+2) mod 5
    __half2 t[5];      // prefetched slice
    float2  mk;        // prefetched mask pair

    // ---- prologue: slices d0-2 .. d0+2 -> slots 0..4 ----
    #pragma unroll
    for (int i = 0; i < 5; i++) {
        const int s = d0 - 2 + i;
        const bool ok = (unsigned)s < DD;
        const size_t o = (size_t)(ok ? s : 0) * (SLICE / 2);
        __half2 tmp[5];
        load_slice_h(p4, pc, o, ok, tmp);
        #pragma unroll
        for (int c = 0; c < 5; c++) v[c][i] = tmp[c];
    }
    const float* __restrict__ Mp = M + (size_t)n * VOL + 2u * (size_t)p2
                                     + (size_t)d0 * SLICE;
    // prefetch slice d0+3 and mask for od = d0
    {
        const int s = d0 + 3;
        const bool ok = (unsigned)s < DD;
        const size_t o = (size_t)(ok ? s : 0) * (SLICE / 2);
        load_slice_h(p4, pc, o, ok, t);
        mk = *reinterpret_cast<const float2*>(Mp);
    }

    float sl = 0.f, sm = 0.f;

    // ---- main loop: 20 outputs, 4 groups of 5 (slot indices static) ----
    #pragma unroll
    for (int g = 0; g < 4; g++) {
        #pragma unroll
        for (int u = 0; u < 5; u++) {
            const int k  = g * 5 + u;
            const int od = d0 + k;

            // 1) blur in half2, convert results to fp32
            float2 a[5];
            #pragma unroll
            for (int c = 0; c < 5; c++) {
                __half2 bh = blur5h(v[c][(u + 0) % 5], v[c][(u + 1) % 5],
                                    v[c][(u + 2) % 5], v[c][(u + 3) % 5],
                                    v[c][(u + 4) % 5], hw0, hw1, hw2);
                a[c] = __half22float2(bh);
            }

            {
                float cross = a[2].x - a[0].x * a[1].x;
                float varI  = fmaxf(a[3].x - a[0].x * a[0].x, 0.f) + 1e-5f;
                float varJ  = fmaxf(a[4].x - a[1].x * a[1].x, 0.f) + 1e-5f;
                float lncc  = 1.f - cross * rsqrtf(varI * varJ);
                sl += lncc * mk.x;
                sm += mk.x;
            }
            {
                float cross = a[2].y - a[0].y * a[1].y;
                float varI  = fmaxf(a[3].y - a[0].y * a[0].y, 0.f) + 1e-5f;
                float varJ  = fmaxf(a[4].y - a[1].y * a[1].y, 0.f) + 1e-5f;
                float lncc  = 1.f - cross * rsqrtf(varI * varJ);
                sl += lncc * mk.y;
                sm += mk.y;
            }

            // 2) commit prefetched slice od+3 into slot u (was od-2, now dead)
            #pragma unroll
            for (int c = 0; c < 5; c++) v[c][u] = t[c];

            // 3) issue prefetch of slice od+4 and mask of od+1
            {
                const int s = od + 4;
                const bool ok = (unsigned)s < DD;
                const size_t o = (size_t)(ok ? s : 0) * (SLICE / 2);
                load_slice_h(p4, pc, o, ok, t);
                const int kn = (k < DSEG - 1) ? k + 1 : k;   // stay in-bounds
                mk = *reinterpret_cast<const float2*>(Mp + (size_t)kn * SLICE);
            }
        }
    }

    // ---- block reduction ----
    #pragma unroll
    for (int o = 16; o > 0; o >>= 1) {
        sl += __shfl_down_sync(0xFFFFFFFFu, sl, o);
        sm += __shfl_down_sync(0xFFFFFFFFu, sm, o);
    }
    __shared__ float rl[8], rm[8];
    const int lane = threadIdx.x & 31, wid = threadIdx.x >> 5;
    if (lane == 0) { rl[wid] = sl; rm[wid] = sm; }
    __syncthreads();
    if (threadIdx.x == 0) {
        float tl = 0.f, tm = 0.f;
        #pragma unroll
        for (int i = 0; i < 8; i++) { tl += rl[i]; tm += rm[i]; }
        atomicAdd(&g_sum[0], (double)tl);
        atomicAdd(&g_sum[1], (double)tm);
        __threadfence();
        const unsigned tk = atomicAdd(&g_ticket, 1u);
        if (tk == (unsigned)(NBLK_B - 1)) {
            const double s0 = atomicAdd(&g_sum[0], 0.0);
            const double s1 = atomicAdd(&g_sum[1], 0.0);
            out[0] = (float)(s0 / (s1 + 1e-8));
        }
    }
}

// ---------------------------------------------------------------------------

extern "C" void kernel_launch(void* const* d_in, const int* in_sizes, int n_in,
                              void* d_out, int out_size)
{
    const float* A = (const float*)d_in[0];  // image_A
    const float* B = (const float*)d_in[1];  // image_B
    const float* M = (const float*)d_in[2];  // mask_A
    float* out = (float*)d_out;

    dim3 gA(WW / 32, HH / 32, NB * DD);      // (7, 6, 320)
    lncc_blur_wh<<<gA, 256>>>(A, B);

    lncc_d_march<<<NBLK_B, 256>>>(M, out);
}

// round 17
// speedup vs baseline: 1.3236x; 1.0094x over previous
#include <cuda_runtime.h>
#include <cuda_fp16.h>

#define NB 2
#define DD 160
#define HH 192
#define WW 224
#define SLICE (HH*WW)          // 43008
#define VOL   (DD*SLICE)       // 6881280
#define TOT   (NB*VOL)         // 13762560

#define W0 0.05448868454964294f
#define W1 0.24420134200323332f
#define W2 0.40261994689424753f

// Interleaved fp16 mid: channels 0..3 packed as uint4 (4x half2) per x-pair,
// channel 4 separate as half2. Indexed by idx2 = n*(VOL/2) + s*(SLICE/2) + p2.
__device__ uint4     g_mid4[TOT / 2];    // 110 MB
__device__ __half2   g_midc[TOT / 2];    // 27.5 MB
__device__ double    g_sum[2];
__device__ unsigned  g_ticket = 0;

// ---------------------------------------------------------------------------
// packed f32x2 helpers (sm_103a): full fp32 precision, 2x rate.
// ---------------------------------------------------------------------------
__device__ __forceinline__ float2 add2(float2 a, float2 b) {
    float2 d;
    asm("{\n\t.reg .b64 x,y,w;\n\t"
        "mov.b64 x,{%2,%3};\n\tmov.b64 y,{%4,%5};\n\t"
        "add.rn.f32x2 w,x,y;\n\tmov.b64 {%0,%1},w;\n\t}"
        : "=f"(d.x), "=f"(d.y)
        : "f"(a.x), "f"(a.y), "f"(b.x), "f"(b.y));
    return d;
}
__device__ __forceinline__ float2 mul2(float2 a, float2 b) {
    float2 d;
    asm("{\n\t.reg .b64 x,y,w;\n\t"
        "mov.b64 x,{%2,%3};\n\tmov.b64 y,{%4,%5};\n\t"
        "mul.rn.f32x2 w,x,y;\n\tmov.b64 {%0,%1},w;\n\t}"
        : "=f"(d.x), "=f"(d.y)
        : "f"(a.x), "f"(a.y), "f"(b.x), "f"(b.y));
    return d;
}
__device__ __forceinline__ float2 fma2(float2 a, float2 b, float2 c) {
    float2 d;
    asm("{\n\t.reg .b64 x,y,z,w;\n\t"
        "mov.b64 x,{%2,%3};\n\tmov.b64 y,{%4,%5};\n\tmov.b64 z,{%6,%7};\n\t"
        "fma.rn.f32x2 w,x,y,z;\n\tmov.b64 {%0,%1},w;\n\t}"
        : "=f"(d.x), "=f"(d.y)
        : "f"(a.x), "f"(a.y), "f"(b.x), "f"(b.y), "f"(c.x), "f"(c.y));
    return d;
}

__device__ __forceinline__ float2 blur5(float2 v0, float2 v1, float2 v2,
                                        float2 v3, float2 v4,
                                        float2 w0, float2 w1, float2 w2)
{
    float2 t = add2(v0, v4);
    float2 u = add2(v1, v3);
    float2 s = mul2(w0, t);
    s = fma2(w1, u, s);
    s = fma2(w2, v2, s);
    return s;
}

// half2 blur (H and D axes). LNCC is scale-invariant; fp16 blur rounding was
// measured to leave rel_err unchanged (R16).
__device__ __forceinline__ __half2 blur5h(__half2 v0, __half2 v1, __half2 v2,
                                          __half2 v3, __half2 v4,
                                          __half2 w0, __half2 w1, __half2 w2)
{
    __half2 s = __hmul2(w0, __hadd2(v0, v4));
    s = __hfma2(w1, __hadd2(v1, v3), s);
    s = __hfma2(w2, v2, s);
    return s;
}

// ---------------------------------------------------------------------------
// Kernel A: y-marching W+H blur. Thread owns x-pair p, marches a 48-row
// y-segment with a 5-slot rolling buffer of W-blurred rows held in half2
// (25 regs). W-blur in f32x2 from raw fp32; H-blur in half2. No smem/barriers.
// Block = 224 threads: threads 0-111 -> segment 2*by, 112-223 -> 2*by+1.
// ---------------------------------------------------------------------------
#define YSEG 48
#define NP   (WW/2)     // 112 x-pairs

struct RawRow { float2 al, ao, ar, bl, bo, br; };

__device__ __forceinline__ RawRow load_row(const float* __restrict__ Ib,
                                           const float* __restrict__ Jb,
                                           int s, int p)
{
    RawRow r;
    const bool okY = (unsigned)s < HH;
    const bool okL = okY && (p > 0);
    const bool okR = okY && (p < NP - 1);
    const int  o   = s * WW + 2 * p;
    const float2 z = make_float2(0.f, 0.f);
    r.ao = okY ? *reinterpret_cast<const float2*>(Ib + o)     : z;
    r.bo = okY ? *reinterpret_cast<const float2*>(Jb + o)     : z;
    r.al = okL ? *reinterpret_cast<const float2*>(Ib + o - 2) : z;
    r.bl = okL ? *reinterpret_cast<const float2*>(Jb + o - 2) : z;
    r.ar = okR ? *reinterpret_cast<const float2*>(Ib + o + 2) : z;
    r.br = okR ? *reinterpret_cast<const float2*>(Jb + o + 2) : z;
    return r;
}

// W-blur one raw row: 5 channels in f32x2, commit as half2.
__device__ __forceinline__ void wblur_row(const RawRow& r, __half2* dst,
                                          float2 w0, float2 w1, float2 w2)
{
    const float2 va0 = r.al;
    const float2 va2 = r.ao;
    const float2 va4 = r.ar;
    const float2 va1 = make_float2(r.al.y, r.ao.x);
    const float2 va3 = make_float2(r.ao.y, r.ar.x);
    const float2 vb0 = r.bl;
    const float2 vb2 = r.bo;
    const float2 vb4 = r.br;
    const float2 vb1 = make_float2(r.bl.y, r.bo.x);
    const float2 vb3 = make_float2(r.bo.y, r.br.x);

    float2 s0 = blur5(va0, va1, va2, va3, va4, w0, w1, w2);
    float2 s1 = blur5(vb0, vb1, vb2, vb3, vb4, w0, w1, w2);
    float2 s2 = blur5(mul2(va0, vb0), mul2(va1, vb1), mul2(va2, vb2),
                      mul2(va3, vb3), mul2(va4, vb4), w0, w1, w2);
    float2 s3 = blur5(mul2(va0, va0), mul2(va1, va1), mul2(va2, va2),
                      mul2(va3, va3), mul2(va4, va4), w0, w1, w2);
    float2 s4 = blur5(mul2(vb0, vb0), mul2(vb1, vb1), mul2(vb2, vb2),
                      mul2(vb3, vb3), mul2(vb4, vb4), w0, w1, w2);
    dst[0] = __floats2half2_rn(s0.x, s0.y);
    dst[1] = __floats2half2_rn(s1.x, s1.y);
    dst[2] = __floats2half2_rn(s2.x, s2.y);
    dst[3] = __floats2half2_rn(s3.x, s3.y);
    dst[4] = __floats2half2_rn(s4.x, s4.y);
}

__global__ void __launch_bounds__(224, 3) lncc_blur_wh(const float* __restrict__ I,
                                                       const float* __restrict__ J)
{
    const int tid   = threadIdx.x;
    const int strip = tid / NP;          // 0 or 1
    const int p     = tid - strip * NP;  // x-pair 0..111
    const int nd    = blockIdx.z;        // n*DD + d
    const int seg   = blockIdx.y * 2 + strip;
    const int y0    = seg * YSEG;

    if (nd == 0 && blockIdx.y == 0 && tid == 0) {
        g_sum[0] = 0.0;
        g_sum[1] = 0.0;
        g_ticket = 0u;
    }

    const float* __restrict__ Ib = I + (size_t)nd * SLICE;
    const float* __restrict__ Jb = J + (size_t)nd * SLICE;

    const float2  w0  = make_float2(W0, W0);
    const float2  w1  = make_float2(W1, W1);
    const float2  w2  = make_float2(W2, W2);
    const __half2 hw0 = __float2half2_rn(W0);
    const __half2 hw1 = __float2half2_rn(W1);
    const __half2 hw2 = __float2half2_rn(W2);

    __half2 v[5][5];    // [channel][slot], slot(row s) = (s - y0 + 2) mod 5
    RawRow  traw;       // prefetched raw row

    // ---- prologue: rows y0-2 .. y0+2 -> slots 0..4 ----
    #pragma unroll
    for (int i = 0; i < 5; i++) {
        RawRow r = load_row(Ib, Jb, y0 - 2 + i, p);
        __half2 tmp[5];
        wblur_row(r, tmp, w0, w1, w2);
        #pragma unroll
        for (int c = 0; c < 5; c++) v[c][i] = tmp[c];
    }
    // prefetch raw row y0+3
    traw = load_row(Ib, Jb, y0 + 3, p);

    const size_t obase = (size_t)nd * (SLICE / 2) + p;

    // one marching step: output row od = y0 + K, slot = K % 5 (static)
    #define ASTEP(U, K)                                                         \
    {                                                                           \
        const int od = y0 + (K);                                                \
        __half2 h[5];                                                           \
        _Pragma("unroll")                                                       \
        for (int c = 0; c < 5; c++) {                                           \
            h[c] = blur5h(v[c][((U) + 0) % 5], v[c][((U) + 1) % 5],             \
                          v[c][((U) + 2) % 5], v[c][((U) + 3) % 5],             \
                          v[c][((U) + 4) % 5], hw0, hw1, hw2);                  \
        }                                                                       \
        uint4 u4;                                                               \
        *reinterpret_cast<__half2*>(&u4.x) = h[0];                              \
        *reinterpret_cast<__half2*>(&u4.y) = h[1];                              \
        *reinterpret_cast<__half2*>(&u4.z) = h[2];                              \
        *reinterpret_cast<__half2*>(&u4.w) = h[3];                              \
        const size_t oi = obase + (size_t)od * (WW / 2);                        \
        g_mid4[oi] = u4;                                                        \
        g_midc[oi] = h[4];                                                      \
        __half2 wn[5];                                                          \
        wblur_row(traw, wn, w0, w1, w2);                                        \
        _Pragma("unroll")                                                       \
        for (int c = 0; c < 5; c++) v[c][(U)] = wn[c];                          \
        traw = load_row(Ib, Jb, od + 4, p);                                     \
    }

    // ---- main: 9 groups of 5 + 3 tail steps = 48 outputs ----
    #pragma unroll
    for (int g = 0; g < 9; g++) {
        ASTEP(0, g * 5 + 0)
        ASTEP(1, g * 5 + 1)
        ASTEP(2, g * 5 + 2)
        ASTEP(3, g * 5 + 3)
        ASTEP(4, g * 5 + 4)
    }
    ASTEP(0, 45)
    ASTEP(1, 46)
    ASTEP(2, 47)

    #undef ASTEP
}

// ---------------------------------------------------------------------------
// Kernel B: D-marching blur (R16 version — best measured B).
// ---------------------------------------------------------------------------
#define DSEG 20
#define NSEG (DD/DSEG)             // 8
#define P2   (SLICE/2)             // 21504
#define BLK_P (P2/256)             // 84
#define NBLK_B (NB*NSEG*BLK_P)     // 1344

__device__ __forceinline__ void load_slice_h(const uint4* p4, const __half2* pc,
                                             size_t o, bool ok, __half2* dst)
{
    if (ok) {
        const uint4 u = p4[o];
        dst[0] = *reinterpret_cast<const __half2*>(&u.x);
        dst[1] = *reinterpret_cast<const __half2*>(&u.y);
        dst[2] = *reinterpret_cast<const __half2*>(&u.z);
        dst[3] = *reinterpret_cast<const __half2*>(&u.w);
        dst[4] = pc[o];
    } else {
        const __half2 z = __float2half2_rn(0.f);
        #pragma unroll
        for (int c = 0; c < 5; c++) dst[c] = z;
    }
}

__global__ void __launch_bounds__(256, 4) lncc_d_march(const float* __restrict__ M,
                                                       float* __restrict__ out)
{
    const int blk = blockIdx.x;
    const int n   = blk / (NSEG * BLK_P);
    const int r   = blk - n * (NSEG * BLK_P);
    const int seg = r / BLK_P;
    const int pb  = r - seg * BLK_P;
    const int p2  = pb * 256 + threadIdx.x;
    const int d0  = seg * DSEG;                // multiple of 5

    const __half2 hw0 = __float2half2_rn(W0);
    const __half2 hw1 = __float2half2_rn(W1);
    const __half2 hw2 = __float2half2_rn(W2);

    const uint4*   __restrict__ p4 = g_mid4 + (size_t)n * (VOL / 2) + p2;
    const __half2* __restrict__ pc = g_midc + (size_t)n * (VOL / 2) + p2;

    __half2 v[5][5];   // [channel][slot], slot(s) = (s+2) mod 5
    __half2 t[5];      // prefetched slice
    float2  mk;        // prefetched mask pair

    // ---- prologue: slices d0-2 .. d0+2 -> slots 0..4 ----
    #pragma unroll
    for (int i = 0; i < 5; i++) {
        const int s = d0 - 2 + i;
        const bool ok = (unsigned)s < DD;
        const size_t o = (size_t)(ok ? s : 0) * (SLICE / 2);
        __half2 tmp[5];
        load_slice_h(p4, pc, o, ok, tmp);
        #pragma unroll
        for (int c = 0; c < 5; c++) v[c][i] = tmp[c];
    }
    const float* __restrict__ Mp = M + (size_t)n * VOL + 2u * (size_t)p2
                                     + (size_t)d0 * SLICE;
    // prefetch slice d0+3 and mask for od = d0
    {
        const int s = d0 + 3;
        const bool ok = (unsigned)s < DD;
        const size_t o = (size_t)(ok ? s : 0) * (SLICE / 2);
        load_slice_h(p4, pc, o, ok, t);
        mk = *reinterpret_cast<const float2*>(Mp);
    }

    float sl = 0.f, sm = 0.f;

    // ---- main loop: 20 outputs, 4 groups of 5 (slot indices static) ----
    #pragma unroll
    for (int g = 0; g < 4; g++) {
        #pragma unroll
        for (int u = 0; u < 5; u++) {
            const int k  = g * 5 + u;
            const int od = d0 + k;

            // 1) blur in half2, convert results to fp32
            float2 a[5];
            #pragma unroll
            for (int c = 0; c < 5; c++) {
                __half2 bh = blur5h(v[c][(u + 0) % 5], v[c][(u + 1) % 5],
                                    v[c][(u + 2) % 5], v[c][(u + 3) % 5],
                                    v[c][(u + 4) % 5], hw0, hw1, hw2);
                a[c] = __half22float2(bh);
            }

            {
                float cross = a[2].x - a[0].x * a[1].x;
                float varI  = fmaxf(a[3].x - a[0].x * a[0].x, 0.f) + 1e-5f;
                float varJ  = fmaxf(a[4].x - a[1].x * a[1].x, 0.f) + 1e-5f;
                float lncc  = 1.f - cross * rsqrtf(varI * varJ);
                sl += lncc * mk.x;
                sm += mk.x;
            }
            {
                float cross = a[2].y - a[0].y * a[1].y;
                float varI  = fmaxf(a[3].y - a[0].y * a[0].y, 0.f) + 1e-5f;
                float varJ  = fmaxf(a[4].y - a[1].y * a[1].y, 0.f) + 1e-5f;
                float lncc  = 1.f - cross * rsqrtf(varI * varJ);
                sl += lncc * mk.y;
                sm += mk.y;
            }

            // 2) commit prefetched slice od+3 into slot u (was od-2, now dead)
            #pragma unroll
            for (int c = 0; c < 5; c++) v[c][u] = t[c];

            // 3) issue prefetch of slice od+4 and mask of od+1
            {
                const int s = od + 4;
                const bool ok = (unsigned)s < DD;
                const size_t o = (size_t)(ok ? s : 0) * (SLICE / 2);
                load_slice_h(p4, pc, o, ok, t);
                const int kn = (k < DSEG - 1) ? k + 1 : k;   // stay in-bounds
                mk = *reinterpret_cast<const float2*>(Mp + (size_t)kn * SLICE);
            }
        }
    }

    // ---- block reduction ----
    #pragma unroll
    for (int o = 16; o > 0; o >>= 1) {
        sl += __shfl_down_sync(0xFFFFFFFFu, sl, o);
        sm += __shfl_down_sync(0xFFFFFFFFu, sm, o);
    }
    __shared__ float rl[8], rm[8];
    const int lane = threadIdx.x & 31, wid = threadIdx.x >> 5;
    if (lane == 0) { rl[wid] = sl; rm[wid] = sm; }
    __syncthreads();
    if (threadIdx.x == 0) {
        float tl = 0.f, tm = 0.f;
        #pragma unroll
        for (int i = 0; i < 8; i++) { tl += rl[i]; tm += rm[i]; }
        atomicAdd(&g_sum[0], (double)tl);
        atomicAdd(&g_sum[1], (double)tm);
        __threadfence();
        const unsigned tk = atomicAdd(&g_ticket, 1u);
        if (tk == (unsigned)(NBLK_B - 1)) {
            const double s0 = atomicAdd(&g_sum[0], 0.0);
            const double s1 = atomicAdd(&g_sum[1], 0.0);
            out[0] = (float)(s0 / (s1 + 1e-8));
        }
    }
}

// ---------------------------------------------------------------------------

extern "C" void kernel_launch(void* const* d_in, const int* in_sizes, int n_in,
                              void* d_out, int out_size)
{
    const float* A = (const float*)d_in[0];  // image_A
    const float* B = (const float*)d_in[1];  // image_B
    const float* M = (const float*)d_in[2];  // mask_A
    float* out = (float*)d_out;

    dim3 gA(1, 2, NB * DD);                  // 640 blocks, 224 threads
    lncc_blur_wh<<<gA, 224>>>(A, B);

    lncc_d_march<<<NBLK_B, 256>>>(M, out);
}